// round 1
// baseline (speedup 1.0000x reference)
#include <cuda_runtime.h>
#include <cuda_bf16.h>

// Output: [B=64, n_scales=4, 256, 256, 3] float32, scales sorted: 32,64,128,256.
// Each thread writes exactly one float4 (4 consecutive floats) of the output.
// Rows are 768 floats = 192 float4, 16B-aligned everywhere.

#define B_IMGS   64
#define HW       256
#define CH       3
#define ROWF     (HW * CH)          // 768 floats per row
#define ROW4     (ROWF / 4)         // 192 float4 per row
#define IMG_F    (HW * HW * CH)     // 196608 floats per image/plane
#define TOT4     (B_IMGS * 4 * HW * ROW4)  // 12,582,912 float4 total output

__global__ void __launch_bounds__(256)
msp_kernel(const float* __restrict__ in, float4* __restrict__ out4)
{
    int i = blockIdx.x * blockDim.x + threadIdx.x;
    if (i >= TOT4) return;

    // i = row * 192 + t ; row = (b*4 + si)*256 + y
    unsigned ui   = (unsigned)i;
    unsigned row  = ui / 192u;
    int      t    = (int)(ui - row * 192u);     // float4 index within row
    int      y    = (int)(row & 255u);
    unsigned plane = row >> 8;                  // b*4 + si
    int      si   = (int)(plane & 3u);
    int      b    = (int)(plane >> 2);

    if (si == 3) {
        // Native 256x256 pass-through: straight float4 copy.
        const float4* in4 = (const float4*)in;
        out4[i] = in4[(b * HW + y) * ROW4 + t];
        return;
    }

    const int s = 32 << si;            // 32, 64, 128
    const int p = (HW - s) >> 1;       // centered pad

    float4 v = make_float4(0.f, 0.f, 0.f, 0.f);

    if (y >= p && y < p + s) {
        const float r  = 255.0f / (float)(s - 1);
        const float fy = (float)(y - p) * r;
        int   y0 = (int)fy;           if (y0 > 255) y0 = 255;
        int   y1 = min(y0 + 1, 255);
        const float wy = fy - (float)y0;

        const float* __restrict__ row0 = in + (b * HW + y0) * ROWF;
        const float* __restrict__ row1 = in + (b * HW + y1) * ROWF;

        float res[4];
        const int f0 = t * 4;
        #pragma unroll
        for (int k = 0; k < 4; k++) {
            const int f = f0 + k;                 // float index within row (0..767)
            const int x = (int)((unsigned)f / 3u);
            const int c = f - x * 3;
            float val = 0.f;
            if (x >= p && x < p + s) {
                const float fx = (float)(x - p) * r;
                int   x0 = (int)fx;       if (x0 > 255) x0 = 255;
                int   x1 = min(x0 + 1, 255);
                const float wx  = fx - (float)x0;
                const float omw = 1.0f - wx;
                const float top = row0[x0 * 3 + c] * omw + row0[x1 * 3 + c] * wx;
                const float bot = row1[x0 * 3 + c] * omw + row1[x1 * 3 + c] * wx;
                val = top * (1.0f - wy) + bot * wy;
            }
            res[k] = val;
        }
        v = make_float4(res[0], res[1], res[2], res[3]);
    }

    out4[i] = v;
}

extern "C" void kernel_launch(void* const* d_in, const int* in_sizes, int n_in,
                              void* d_out, int out_size)
{
    const float* images = (const float*)d_in[0];
    float4* out4 = (float4*)d_out;

    const int threads = 256;
    const int blocks  = (TOT4 + threads - 1) / threads;  // 49152
    msp_kernel<<<blocks, threads>>>(images, out4);
}

// round 2
// speedup vs baseline: 1.0109x; 1.0109x over previous
#include <cuda_runtime.h>
#include <cuda_bf16.h>

// Output: [B=64, n_scales=4, 256, 256, 3] float32, scales sorted: 32,64,128,256.
// One block per output row; 192 threads = one float4 each (768 floats/row).
// grid = (y=256, si=4, b=64). All control flow uniform per block except the
// x-direction pad boundary inside small-scale rows.

#define HW    256
#define ROWF  (HW * 3)     // 768 floats per row
#define ROW4  (ROWF / 4)   // 192 float4 per row

__global__ void __launch_bounds__(192)
msp_kernel(const float* __restrict__ in, float4* __restrict__ out4)
{
    const int t  = threadIdx.x;        // float4 index within row, 0..191
    const int y  = blockIdx.x;         // 0..255
    const int si = blockIdx.y;         // 0..3
    const int b  = blockIdx.z;         // 0..63

    // Output float4 index: (((b*4 + si)*256 + y) * 192 + t)
    const long long oi = (((long long)(b * 4 + si) * HW + y) * ROW4) + t;

    if (si == 3) {
        // Native 256x256 pass-through: straight float4 copy (fully coalesced).
        const float4* __restrict__ in4 = (const float4*)in;
        out4[oi] = in4[(b * HW + y) * ROW4 + t];
        return;
    }

    const int s = 32 << si;            // 32, 64, 128
    const int p = (HW - s) >> 1;       // centered pad

    if (y < p || y >= p + s) {
        // Pure pad row: zero store.
        out4[oi] = make_float4(0.f, 0.f, 0.f, 0.f);
        return;
    }

    const float r  = 255.0f / (float)(s - 1);
    const float fy = (float)(y - p) * r;
    int   y0 = (int)fy;           if (y0 > 255) y0 = 255;
    int   y1 = min(y0 + 1, 255);
    const float wy  = fy - (float)y0;
    const float omy = 1.0f - wy;

    const float* __restrict__ row0 = in + (b * HW + y0) * ROWF;
    const float* __restrict__ row1 = in + (b * HW + y1) * ROWF;

    float res[4];
    const int f0 = t * 4;
    #pragma unroll
    for (int k = 0; k < 4; k++) {
        const int f = f0 + k;                    // float index within row (0..767)
        const int x = (int)((unsigned)f / 3u);   // pixel
        const int c = f - x * 3;                 // channel
        float val = 0.f;
        if (x >= p && x < p + s) {
            const float fx = (float)(x - p) * r;
            int   x0 = (int)fx;       if (x0 > 255) x0 = 255;
            int   x1 = min(x0 + 1, 255);
            const float wx  = fx - (float)x0;
            const float omw = 1.0f - wx;
            const float top = __ldg(row0 + x0 * 3 + c) * omw + __ldg(row0 + x1 * 3 + c) * wx;
            const float bot = __ldg(row1 + x0 * 3 + c) * omw + __ldg(row1 + x1 * 3 + c) * wx;
            val = top * omy + bot * wy;
        }
        res[k] = val;
    }
    out4[oi] = make_float4(res[0], res[1], res[2], res[3]);
}

extern "C" void kernel_launch(void* const* d_in, const int* in_sizes, int n_in,
                              void* d_out, int out_size)
{
    const float* images = (const float*)d_in[0];
    float4* out4 = (float4*)d_out;

    dim3 grid(HW, 4, 64);   // y, scale-index, batch
    dim3 block(192);
    msp_kernel<<<grid, block>>>(images, out4);
}